// round 5
// baseline (speedup 1.0000x reference)
#include <cuda_runtime.h>
#include <float.h>

#define EPS 1e-5f
#define NEG 0.2f

typedef unsigned long long ull;

__device__ __forceinline__ ull fma2(ull a, ull b, ull c) {
    ull d; asm("fma.rn.f32x2 %0, %1, %2, %3;" : "=l"(d) : "l"(a), "l"(b), "l"(c)); return d;
}
__device__ __forceinline__ ull add2(ull a, ull b) {
    ull d; asm("add.rn.f32x2 %0, %1, %2;" : "=l"(d) : "l"(a), "l"(b)); return d;
}
__device__ __forceinline__ ull mul2(ull a, ull b) {
    ull d; asm("mul.rn.f32x2 %0, %1, %2;" : "=l"(d) : "l"(a), "l"(b)); return d;
}
__device__ __forceinline__ ull pk(float lo, float hi) {
    ull r; asm("mov.b64 %0, {%1, %2};" : "=l"(r) : "f"(lo), "f"(hi)); return r;
}
__device__ __forceinline__ ull dup(float v) { return pk(v, v); }
__device__ __forceinline__ void unpk(ull v, float& lo, float& hi) {
    asm("mov.b64 {%0, %1}, %2;" : "=f"(lo), "=f"(hi) : "l"(v));
}
// lrelu(v) = 0.6*v + 0.4*|v|  (== v for v>0, 0.2v for v<0)
__device__ __forceinline__ ull lrelu2(ull v) {
    ull av = v & 0x7FFFFFFF7FFFFFFFULL;
    return fma2(dup(0.4f), av, mul2(dup(0.6f), v));
}

// BN-folded weights (setup kernel writes, main kernel reads)
__device__ float g_wt[64 * 6], g_bt[64];
__device__ float g_wp1[64 * 3], g_bp1[64];
__device__ float g_wg1[16 * 6], g_bg1[16];
__device__ float g_wa1[16 * 6], g_ba1[16];

__global__ void fold_kernel(
    const float* __restrict__ trans_w, const float* __restrict__ trans_g,
    const float* __restrict__ trans_b, const float* __restrict__ trans_m,
    const float* __restrict__ trans_v,
    const float* __restrict__ pos_w1, const float* __restrict__ pos_g,
    const float* __restrict__ pos_b, const float* __restrict__ pos_m,
    const float* __restrict__ pos_v,
    const float* __restrict__ gate_w1, const float* __restrict__ gate_g,
    const float* __restrict__ gate_b, const float* __restrict__ gate_m,
    const float* __restrict__ gate_v,
    const float* __restrict__ attn_w1, const float* __restrict__ attn_g,
    const float* __restrict__ attn_b, const float* __restrict__ attn_m,
    const float* __restrict__ attn_v)
{
    int i = threadIdx.x;
    if (i < 64) {
        float s = trans_g[i] * rsqrtf(trans_v[i] + EPS);
        #pragma unroll
        for (int j = 0; j < 6; j++) g_wt[i * 6 + j] = trans_w[i * 6 + j] * s;
        g_bt[i] = trans_b[i] - trans_m[i] * s;
        float sp = pos_g[i] * rsqrtf(pos_v[i] + EPS);
        #pragma unroll
        for (int j = 0; j < 3; j++) g_wp1[i * 3 + j] = pos_w1[i * 3 + j] * sp;
        g_bp1[i] = pos_b[i] - pos_m[i] * sp;
    }
    if (i < 16) {
        float sg = gate_g[i] * rsqrtf(gate_v[i] + EPS);
        #pragma unroll
        for (int j = 0; j < 6; j++) g_wg1[i * 6 + j] = gate_w1[i * 6 + j] * sg;
        g_bg1[i] = gate_b[i] - gate_m[i] * sg;
        float sa = attn_g[i] * rsqrtf(attn_v[i] + EPS);
        #pragma unroll
        for (int j = 0; j < 6; j++) g_wa1[i * 6 + j] = attn_w1[i * 6 + j] * sa;
        g_ba1[i] = attn_b[i] - attn_m[i] * sa;
    }
}

// Load H ulls (H even) from a 16B-aligned shared row slice via float4.
template<int H, int OFF>
__device__ __forceinline__ void load_row(const float* row, ull* r) {
    const float4* p = reinterpret_cast<const float4*>(row + OFF);
    #pragma unroll
    for (int i = 0; i < H / 2; i++) {
        float4 v = p[i];
        r[2 * i]     = pk(v.x, v.y);
        r[2 * i + 1] = pk(v.z, v.w);
    }
}

// Process one k-half (H ulls, starting at float offset OFF): pos_enc -> attn
// logits -> local softmax -> trans -> merge into running online-softmax state.
template<int H, int OFF>
__device__ __forceinline__ void half_pass(
    const float* phg, const float* ahg, const float* xg, const ull* gmr,
    const float* w2sh, const float* wa2sh,
    const float* pos_b2, const float* attn_b2,
    int c0, int c1,
    float& M0, float& M1, ull& SE0, ull& SE1, ull& SA0, ull& SA1,
    float& MX0, float& MX1)
{
    // pos_enc
    ull pe0[H], pe1[H];
    {
        ull B0 = dup(pos_b2[c0]), B1 = dup(pos_b2[c1]);
        #pragma unroll
        for (int q = 0; q < H; q++) { pe0[q] = B0; pe1[q] = B1; }
    }
    #pragma unroll 2
    for (int jc = 0; jc < 16; ++jc) {
        ull w0[4], w1[4];
        #pragma unroll
        for (int t = 0; t < 4; t++) {
            int j = jc * 4 + t;
            w0[t] = dup(w2sh[j * 64 + c0]);
            w1[t] = dup(w2sh[j * 64 + c1]);
        }
        #pragma unroll
        for (int t = 0; t < 4; t++) {
            ull r[H];
            load_row<H, OFF>(phg + (jc * 4 + t) * 20, r);
            #pragma unroll
            for (int q = 0; q < H; q++) {
                pe0[q] = fma2(w0[t], r[q], pe0[q]);
                pe1[q] = fma2(w1[t], r[q], pe1[q]);
            }
        }
    }

    // attn logits (starts from pos_enc + attn bias)
    ull al0[H], al1[H];
    {
        ull B0 = dup(attn_b2[c0]), B1 = dup(attn_b2[c1]);
        #pragma unroll
        for (int q = 0; q < H; q++) {
            al0[q] = add2(pe0[q], B0);
            al1[q] = add2(pe1[q], B1);
        }
    }
    #pragma unroll 2
    for (int jc = 0; jc < 4; ++jc) {
        ull w0[4], w1[4];
        #pragma unroll
        for (int t = 0; t < 4; t++) {
            int j = jc * 4 + t;
            w0[t] = dup(wa2sh[j * 64 + c0]);
            w1[t] = dup(wa2sh[j * 64 + c1]);
        }
        #pragma unroll
        for (int t = 0; t < 4; t++) {
            ull r[H];
            load_row<H, OFF>(ahg + (jc * 4 + t) * 20, r);
            #pragma unroll
            for (int q = 0; q < H; q++) {
                al0[q] = fma2(w0[t], r[q], al0[q]);
                al1[q] = fma2(w1[t], r[q], al1[q]);
            }
        }
    }

    // local softmax: max, exp in place, local sum
    float m0 = -FLT_MAX, m1 = -FLT_MAX;
    #pragma unroll
    for (int q = 0; q < H; q++) {
        float a, bq;
        unpk(al0[q], a, bq); m0 = fmaxf(m0, fmaxf(a, bq));
        unpk(al1[q], a, bq); m1 = fmaxf(m1, fmaxf(a, bq));
    }
    ull se0 = dup(0.f), se1 = dup(0.f);
    #pragma unroll
    for (int q = 0; q < H; q++) {
        float a, bq;
        unpk(al0[q], a, bq);
        al0[q] = pk(__expf(a - m0), __expf(bq - m0));
        se0 = add2(se0, al0[q]);
        unpk(al1[q], a, bq);
        al1[q] = pk(__expf(a - m1), __expf(bq - m1));
        se1 = add2(se1, al1[q]);
    }

    // trans conv (pre-lrelu)
    ull tf0[H], tf1[H];
    {
        ull B0 = dup(g_bt[c0]), B1 = dup(g_bt[c1]);
        #pragma unroll
        for (int q = 0; q < H; q++) { tf0[q] = B0; tf1[q] = B1; }
        #pragma unroll
        for (int i = 0; i < 6; i++) {
            ull wt0 = dup(g_wt[c0 * 6 + i]), wt1 = dup(g_wt[c1 * 6 + i]);
            ull r[H];
            load_row<H, OFF>(xg + i * 20, r);
            #pragma unroll
            for (int q = 0; q < H; q++) {
                tf0[q] = fma2(wt0, r[q], tf0[q]);
                tf1[q] = fma2(wt1, r[q], tf1[q]);
            }
        }
    }

    // local weighted sum + gated max
    ull sa0 = dup(0.f), sa1 = dup(0.f);
    #pragma unroll
    for (int q = 0; q < H; q++) {
        ull gk = gmr[OFF / 2 + q];
        float a, bq;
        ull t0 = add2(lrelu2(tf0[q]), pe0[q]);
        sa0 = fma2(t0, al0[q], sa0);
        unpk(mul2(t0, gk), a, bq);
        MX0 = fmaxf(MX0, fmaxf(a, bq));
        ull t1 = add2(lrelu2(tf1[q]), pe1[q]);
        sa1 = fma2(t1, al1[q], sa1);
        unpk(mul2(t1, gk), a, bq);
        MX1 = fmaxf(MX1, fmaxf(a, bq));
    }

    // merge into running online-softmax state
    {
        float nm = fmaxf(M0, m0);
        ull so = dup(__expf(M0 - nm)), sn = dup(__expf(m0 - nm));
        SE0 = add2(mul2(SE0, so), mul2(se0, sn));
        SA0 = add2(mul2(SA0, so), mul2(sa0, sn));
        M0 = nm;
        nm = fmaxf(M1, m1);
        so = dup(__expf(M1 - nm)); sn = dup(__expf(m1 - nm));
        SE1 = add2(mul2(SE1, so), mul2(se1, sn));
        SA1 = add2(mul2(SA1, so), mul2(sa1, sn));
        M1 = nm;
    }
}

// Block = 128 threads = 4 n-positions (one warp each); each lane owns channels
// (lane, lane+32). k (20) processed in two 16B-aligned halves (12 + 8 floats)
// with online softmax, so peak live registers fit 4 CTAs/SM.
__global__ __launch_bounds__(128, 4) void gsl_main_kernel(
    const float* __restrict__ x,
    const float* __restrict__ pos_w2, const float* __restrict__ pos_b2,
    const float* __restrict__ gate_w2, const float* __restrict__ gate_b2,
    const float* __restrict__ attn_w2, const float* __restrict__ attn_b2,
    float* __restrict__ out)
{
    __shared__ __align__(16) float ph[4 * 64 * 20];   // [g][j][k]
    __shared__ __align__(16) float ah[4 * 16 * 20];   // [g][j][k]
    __shared__ __align__(16) float xsh[4 * 6 * 20];   // [g][ch][k]
    __shared__ __align__(16) float gm[4 * 20];        // [g][k]
    __shared__ float w2sh[64 * 64];                   // [j][c]
    __shared__ float wa2sh[16 * 64];                  // [j][c]
    __shared__ float outsh[64 * 6];                   // [c][g] padded stride 6

    const int tid = threadIdx.x;
    const int b = blockIdx.x >> 11;
    const int n0 = (blockIdx.x & 2047) << 2;

    // ---- cooperative loads: x tile + transposed weights ----
    const float* xb = x + ((size_t)b * 6 * 8192 + n0) * 20;
    for (int idx = tid; idx < 480; idx += 128) {
        int ch = idx / 80; int r = idx - ch * 80;          // r = g*20 + k
        xsh[(r / 20) * 120 + ch * 20 + (r % 20)] = xb[(size_t)ch * 8192 * 20 + r];
    }
    for (int idx = tid; idx < 4096; idx += 128) {
        int c = idx >> 6, j = idx & 63;
        w2sh[j * 64 + c] = pos_w2[idx];
    }
    for (int idx = tid; idx < 1024; idx += 128) {
        int c = idx >> 4, j = idx & 15;
        wa2sh[j * 64 + c] = attn_w2[idx];
    }
    __syncthreads();

    const int g = tid >> 5;
    const int lane = tid & 31;
    float* phg = ph + g * 1280;
    float* ahg = ah + g * 320;
    const float* xg = xsh + g * 120;
    const ull* xgu = reinterpret_cast<const ull*>(xg);   // row i at i*10

    // ---- phase 1 (warp-local): pos_h rows (lane, lane+32) ----
    {
        ull xr[3][10];
        #pragma unroll
        for (int i = 0; i < 3; i++)
            #pragma unroll
            for (int q = 0; q < 10; q++) xr[i][q] = xgu[(3 + i) * 10 + q];

        #pragma unroll
        for (int rr = 0; rr < 2; rr++) {
            int j = lane + rr * 32;
            ull w0 = dup(g_wp1[j * 3 + 0]);
            ull w1 = dup(g_wp1[j * 3 + 1]);
            ull w2d = dup(g_wp1[j * 3 + 2]);
            ull bb = dup(g_bp1[j]);
            ull* dst = reinterpret_cast<ull*>(phg) + j * 10;
            #pragma unroll
            for (int q = 0; q < 10; q++) {
                ull v = fma2(w0, xr[0][q], bb);
                v = fma2(w1, xr[1][q], v);
                v = fma2(w2d, xr[2][q], v);
                dst[q] = lrelu2(v);
            }
        }
    }
    // ---- attn_h rows (lanes 0..15) ----
    if (lane < 16) {
        ull bb = dup(g_ba1[lane]);
        ull acc[10];
        #pragma unroll
        for (int q = 0; q < 10; q++) acc[q] = bb;
        #pragma unroll
        for (int i = 0; i < 6; i++) {
            ull wd = dup(g_wa1[lane * 6 + i]);
            #pragma unroll
            for (int q = 0; q < 10; q++) acc[q] = fma2(wd, xgu[i * 10 + q], acc[q]);
        }
        ull* dst = reinterpret_cast<ull*>(ahg) + lane * 10;
        #pragma unroll
        for (int q = 0; q < 10; q++) dst[q] = lrelu2(acc[q]);
    }
    // ---- gate_map (lanes 0..19) ----
    if (lane < 20) {
        float acc = gate_b2[0];
        #pragma unroll
        for (int j = 0; j < 16; j++) {
            float v = g_bg1[j];
            #pragma unroll
            for (int i = 0; i < 6; i++) v += g_wg1[j * 6 + i] * xg[i * 20 + lane];
            v = v > 0.f ? v : NEG * v;
            acc += gate_w2[j] * v;
        }
        gm[g * 20 + lane] = 1.f / (1.f + __expf(-acc));
    }
    __syncwarp();

    // ---- phase 2: two k-halves with online softmax ----
    const int c0 = lane, c1 = lane + 32;
    const ull* gmr = reinterpret_cast<const ull*>(gm + g * 20);

    float M0 = -FLT_MAX, M1 = -FLT_MAX, MX0 = -FLT_MAX, MX1 = -FLT_MAX;
    ull SE0 = dup(0.f), SE1 = dup(0.f), SA0 = dup(0.f), SA1 = dup(0.f);

    half_pass<6, 0>(phg, ahg, xg, gmr, w2sh, wa2sh, pos_b2, attn_b2,
                    c0, c1, M0, M1, SE0, SE1, SA0, SA1, MX0, MX1);
    half_pass<4, 12>(phg, ahg, xg, gmr, w2sh, wa2sh, pos_b2, attn_b2,
                     c0, c1, M0, M1, SE0, SE1, SA0, SA1, MX0, MX1);

    {
        float a, bq, s, t;
        unpk(SA0, a, bq); unpk(SE0, s, t);
        outsh[c0 * 6 + g] = (a + bq) / (s + t) + MX0;
        unpk(SA1, a, bq); unpk(SE1, s, t);
        outsh[c1 * 6 + g] = (a + bq) / (s + t) + MX1;
    }
    __syncthreads();

    // coalesced-ish output: 64 ch x 4 n as float2 stores
    {
        int c = tid >> 1, h = (tid & 1) * 2;
        float2 v = make_float2(outsh[c * 6 + h], outsh[c * 6 + h + 1]);
        *reinterpret_cast<float2*>(out + ((size_t)b * 64 + c) * 8192 + n0 + h) = v;
    }
}

extern "C" void kernel_launch(void* const* d_in, const int* in_sizes, int n_in,
                              void* d_out, int out_size)
{
    (void)in_sizes; (void)n_in; (void)out_size;
    const float* x = (const float*)d_in[0];

    fold_kernel<<<1, 64>>>(
        (const float*)d_in[1], (const float*)d_in[2], (const float*)d_in[3],
        (const float*)d_in[4], (const float*)d_in[5],
        (const float*)d_in[6], (const float*)d_in[7], (const float*)d_in[8],
        (const float*)d_in[9], (const float*)d_in[10],
        (const float*)d_in[13], (const float*)d_in[14], (const float*)d_in[15],
        (const float*)d_in[16], (const float*)d_in[17],
        (const float*)d_in[20], (const float*)d_in[21], (const float*)d_in[22],
        (const float*)d_in[23], (const float*)d_in[24]);

    gsl_main_kernel<<<16384, 128>>>(
        x,
        (const float*)d_in[11], (const float*)d_in[12],   // pos_w2, pos_b2
        (const float*)d_in[18], (const float*)d_in[19],   // gate_w2, gate_b2
        (const float*)d_in[25], (const float*)d_in[26],   // attn_w2, attn_b2
        (float*)d_out);
}

// round 6
// speedup vs baseline: 1.6367x; 1.6367x over previous
#include <cuda_runtime.h>
#include <float.h>

#define EPS 1e-5f
#define NEG 0.2f

typedef unsigned long long ull;

__device__ __forceinline__ ull fma2(ull a, ull b, ull c) {
    ull d; asm("fma.rn.f32x2 %0, %1, %2, %3;" : "=l"(d) : "l"(a), "l"(b), "l"(c)); return d;
}
__device__ __forceinline__ ull add2(ull a, ull b) {
    ull d; asm("add.rn.f32x2 %0, %1, %2;" : "=l"(d) : "l"(a), "l"(b)); return d;
}
__device__ __forceinline__ ull mul2(ull a, ull b) {
    ull d; asm("mul.rn.f32x2 %0, %1, %2;" : "=l"(d) : "l"(a), "l"(b)); return d;
}
__device__ __forceinline__ ull pk(float lo, float hi) {
    ull r; asm("mov.b64 %0, {%1, %2};" : "=l"(r) : "f"(lo), "f"(hi)); return r;
}
__device__ __forceinline__ ull dup(float v) { return pk(v, v); }
__device__ __forceinline__ void unpk(ull v, float& lo, float& hi) {
    asm("mov.b64 {%0, %1}, %2;" : "=f"(lo), "=f"(hi) : "l"(v));
}
// lrelu(v) = 0.6*v + 0.4*|v|  (== v for v>0, 0.2v for v<0)
__device__ __forceinline__ ull lrelu2(ull v) {
    ull av = v & 0x7FFFFFFF7FFFFFFFULL;
    return fma2(dup(0.4f), av, mul2(dup(0.6f), v));
}

// BN-folded weights (setup kernel writes, main kernel reads)
__device__ float g_wt[64 * 6], g_bt[64];
__device__ float g_wp1[64 * 3], g_bp1[64];
__device__ float g_wg1[16 * 6], g_bg1[16];
__device__ float g_wa1[16 * 6], g_ba1[16];

__global__ void fold_kernel(
    const float* __restrict__ trans_w, const float* __restrict__ trans_g,
    const float* __restrict__ trans_b, const float* __restrict__ trans_m,
    const float* __restrict__ trans_v,
    const float* __restrict__ pos_w1, const float* __restrict__ pos_g,
    const float* __restrict__ pos_b, const float* __restrict__ pos_m,
    const float* __restrict__ pos_v,
    const float* __restrict__ gate_w1, const float* __restrict__ gate_g,
    const float* __restrict__ gate_b, const float* __restrict__ gate_m,
    const float* __restrict__ gate_v,
    const float* __restrict__ attn_w1, const float* __restrict__ attn_g,
    const float* __restrict__ attn_b, const float* __restrict__ attn_m,
    const float* __restrict__ attn_v)
{
    int i = threadIdx.x;
    if (i < 64) {
        float s = trans_g[i] * rsqrtf(trans_v[i] + EPS);
        #pragma unroll
        for (int j = 0; j < 6; j++) g_wt[i * 6 + j] = trans_w[i * 6 + j] * s;
        g_bt[i] = trans_b[i] - trans_m[i] * s;
        float sp = pos_g[i] * rsqrtf(pos_v[i] + EPS);
        #pragma unroll
        for (int j = 0; j < 3; j++) g_wp1[i * 3 + j] = pos_w1[i * 3 + j] * sp;
        g_bp1[i] = pos_b[i] - pos_m[i] * sp;
    }
    if (i < 16) {
        float sg = gate_g[i] * rsqrtf(gate_v[i] + EPS);
        #pragma unroll
        for (int j = 0; j < 6; j++) g_wg1[i * 6 + j] = gate_w1[i * 6 + j] * sg;
        g_bg1[i] = gate_b[i] - gate_m[i] * sg;
        float sa = attn_g[i] * rsqrtf(attn_v[i] + EPS);
        #pragma unroll
        for (int j = 0; j < 6; j++) g_wa1[i * 6 + j] = attn_w1[i * 6 + j] * sa;
        g_ba1[i] = attn_b[i] - attn_m[i] * sa;
    }
}

// Load H ulls (H even) from a 16B-aligned shared row slice via float4.
template<int H, int OFF>
__device__ __forceinline__ void load_row(const float* row, ull* r) {
    const float4* p = reinterpret_cast<const float4*>(row + OFF);
    #pragma unroll
    for (int i = 0; i < H / 2; i++) {
        float4 v = p[i];
        r[2 * i]     = pk(v.x, v.y);
        r[2 * i + 1] = pk(v.z, v.w);
    }
}

// Process one k-half (H ulls, starting at float offset OFF): pos_enc -> attn
// logits -> local softmax -> trans -> merge into running online-softmax state.
template<int H, int OFF>
__device__ __forceinline__ void half_pass(
    const float* phg, const float* ahg, const float* xg, const ull* gmr,
    const float* w2sh, const float* wa2sh,
    const float* pos_b2, const float* attn_b2,
    int c0, int c1,
    float& M0, float& M1, ull& SE0, ull& SE1, ull& SA0, ull& SA1,
    float& MX0, float& MX1)
{
    // pos_enc
    ull pe0[H], pe1[H];
    {
        ull B0 = dup(pos_b2[c0]), B1 = dup(pos_b2[c1]);
        #pragma unroll
        for (int q = 0; q < H; q++) { pe0[q] = B0; pe1[q] = B1; }
    }
    #pragma unroll 2
    for (int jc = 0; jc < 16; ++jc) {
        ull w0[4], w1[4];
        #pragma unroll
        for (int t = 0; t < 4; t++) {
            int j = jc * 4 + t;
            w0[t] = dup(w2sh[j * 64 + c0]);
            w1[t] = dup(w2sh[j * 64 + c1]);
        }
        #pragma unroll
        for (int t = 0; t < 4; t++) {
            ull r[H];
            load_row<H, OFF>(phg + (jc * 4 + t) * 20, r);
            #pragma unroll
            for (int q = 0; q < H; q++) {
                pe0[q] = fma2(w0[t], r[q], pe0[q]);
                pe1[q] = fma2(w1[t], r[q], pe1[q]);
            }
        }
    }

    // attn logits (starts from pos_enc + attn bias)
    ull al0[H], al1[H];
    {
        ull B0 = dup(attn_b2[c0]), B1 = dup(attn_b2[c1]);
        #pragma unroll
        for (int q = 0; q < H; q++) {
            al0[q] = add2(pe0[q], B0);
            al1[q] = add2(pe1[q], B1);
        }
    }
    #pragma unroll 2
    for (int jc = 0; jc < 4; ++jc) {
        ull w0[4], w1[4];
        #pragma unroll
        for (int t = 0; t < 4; t++) {
            int j = jc * 4 + t;
            w0[t] = dup(wa2sh[j * 64 + c0]);
            w1[t] = dup(wa2sh[j * 64 + c1]);
        }
        #pragma unroll
        for (int t = 0; t < 4; t++) {
            ull r[H];
            load_row<H, OFF>(ahg + (jc * 4 + t) * 20, r);
            #pragma unroll
            for (int q = 0; q < H; q++) {
                al0[q] = fma2(w0[t], r[q], al0[q]);
                al1[q] = fma2(w1[t], r[q], al1[q]);
            }
        }
    }

    // local softmax: max, exp in place, local sum
    float m0 = -FLT_MAX, m1 = -FLT_MAX;
    #pragma unroll
    for (int q = 0; q < H; q++) {
        float a, bq;
        unpk(al0[q], a, bq); m0 = fmaxf(m0, fmaxf(a, bq));
        unpk(al1[q], a, bq); m1 = fmaxf(m1, fmaxf(a, bq));
    }
    ull se0 = dup(0.f), se1 = dup(0.f);
    #pragma unroll
    for (int q = 0; q < H; q++) {
        float a, bq;
        unpk(al0[q], a, bq);
        al0[q] = pk(__expf(a - m0), __expf(bq - m0));
        se0 = add2(se0, al0[q]);
        unpk(al1[q], a, bq);
        al1[q] = pk(__expf(a - m1), __expf(bq - m1));
        se1 = add2(se1, al1[q]);
    }

    // trans conv (pre-lrelu)
    ull tf0[H], tf1[H];
    {
        ull B0 = dup(g_bt[c0]), B1 = dup(g_bt[c1]);
        #pragma unroll
        for (int q = 0; q < H; q++) { tf0[q] = B0; tf1[q] = B1; }
        #pragma unroll
        for (int i = 0; i < 6; i++) {
            ull wt0 = dup(g_wt[c0 * 6 + i]), wt1 = dup(g_wt[c1 * 6 + i]);
            ull r[H];
            load_row<H, OFF>(xg + i * 20, r);
            #pragma unroll
            for (int q = 0; q < H; q++) {
                tf0[q] = fma2(wt0, r[q], tf0[q]);
                tf1[q] = fma2(wt1, r[q], tf1[q]);
            }
        }
    }

    // local weighted sum + gated max
    ull sa0 = dup(0.f), sa1 = dup(0.f);
    #pragma unroll
    for (int q = 0; q < H; q++) {
        ull gk = gmr[OFF / 2 + q];
        float a, bq;
        ull t0 = add2(lrelu2(tf0[q]), pe0[q]);
        sa0 = fma2(t0, al0[q], sa0);
        unpk(mul2(t0, gk), a, bq);
        MX0 = fmaxf(MX0, fmaxf(a, bq));
        ull t1 = add2(lrelu2(tf1[q]), pe1[q]);
        sa1 = fma2(t1, al1[q], sa1);
        unpk(mul2(t1, gk), a, bq);
        MX1 = fmaxf(MX1, fmaxf(a, bq));
    }

    // merge into running online-softmax state
    {
        float nm = fmaxf(M0, m0);
        ull so = dup(__expf(M0 - nm)), sn = dup(__expf(m0 - nm));
        SE0 = add2(mul2(SE0, so), mul2(se0, sn));
        SA0 = add2(mul2(SA0, so), mul2(sa0, sn));
        M0 = nm;
        nm = fmaxf(M1, m1);
        so = dup(__expf(M1 - nm)); sn = dup(__expf(m1 - nm));
        SE1 = add2(mul2(SE1, so), mul2(se1, sn));
        SA1 = add2(mul2(SA1, so), mul2(sa1, sn));
        M1 = nm;
    }
}

// Block = 128 threads = 4 n-positions (one warp each); each lane owns channels
// (lane, lane+32). k (20) processed in two 16B-aligned halves (12 + 8 floats)
// with online softmax, so peak live registers fit 4 CTAs/SM.
__global__ __launch_bounds__(128, 4) void gsl_main_kernel(
    const float* __restrict__ x,
    const float* __restrict__ pos_w2, const float* __restrict__ pos_b2,
    const float* __restrict__ gate_w2, const float* __restrict__ gate_b2,
    const float* __restrict__ attn_w2, const float* __restrict__ attn_b2,
    float* __restrict__ out)
{
    __shared__ __align__(16) float ph[4 * 64 * 20];   // [g][j][k]
    __shared__ __align__(16) float ah[4 * 16 * 20];   // [g][j][k]
    __shared__ __align__(16) float xsh[4 * 6 * 20];   // [g][ch][k]
    __shared__ __align__(16) float gm[4 * 20];        // [g][k]
    __shared__ float w2sh[64 * 64];                   // [j][c]
    __shared__ float wa2sh[16 * 64];                  // [j][c]
    __shared__ float outsh[64 * 6];                   // [c][g] padded stride 6

    const int tid = threadIdx.x;
    const int b = blockIdx.x >> 11;
    const int n0 = (blockIdx.x & 2047) << 2;

    // ---- cooperative loads: x tile + transposed weights ----
    const float* xb = x + ((size_t)b * 6 * 8192 + n0) * 20;
    for (int idx = tid; idx < 480; idx += 128) {
        int ch = idx / 80; int r = idx - ch * 80;          // r = g*20 + k
        xsh[(r / 20) * 120 + ch * 20 + (r % 20)] = xb[(size_t)ch * 8192 * 20 + r];
    }
    for (int idx = tid; idx < 4096; idx += 128) {
        int c = idx >> 6, j = idx & 63;
        w2sh[j * 64 + c] = pos_w2[idx];
    }
    for (int idx = tid; idx < 1024; idx += 128) {
        int c = idx >> 4, j = idx & 15;
        wa2sh[j * 64 + c] = attn_w2[idx];
    }
    __syncthreads();

    const int g = tid >> 5;
    const int lane = tid & 31;
    float* phg = ph + g * 1280;
    float* ahg = ah + g * 320;
    const float* xg = xsh + g * 120;
    const ull* xgu = reinterpret_cast<const ull*>(xg);   // row i at i*10

    // ---- phase 1 (warp-local): pos_h rows (lane, lane+32) ----
    {
        ull xr[3][10];
        #pragma unroll
        for (int i = 0; i < 3; i++)
            #pragma unroll
            for (int q = 0; q < 10; q++) xr[i][q] = xgu[(3 + i) * 10 + q];

        #pragma unroll
        for (int rr = 0; rr < 2; rr++) {
            int j = lane + rr * 32;
            ull w0 = dup(g_wp1[j * 3 + 0]);
            ull w1 = dup(g_wp1[j * 3 + 1]);
            ull w2d = dup(g_wp1[j * 3 + 2]);
            ull bb = dup(g_bp1[j]);
            ull* dst = reinterpret_cast<ull*>(phg) + j * 10;
            #pragma unroll
            for (int q = 0; q < 10; q++) {
                ull v = fma2(w0, xr[0][q], bb);
                v = fma2(w1, xr[1][q], v);
                v = fma2(w2d, xr[2][q], v);
                dst[q] = lrelu2(v);
            }
        }
    }
    // ---- attn_h rows (lanes 0..15) ----
    if (lane < 16) {
        ull bb = dup(g_ba1[lane]);
        ull acc[10];
        #pragma unroll
        for (int q = 0; q < 10; q++) acc[q] = bb;
        #pragma unroll
        for (int i = 0; i < 6; i++) {
            ull wd = dup(g_wa1[lane * 6 + i]);
            #pragma unroll
            for (int q = 0; q < 10; q++) acc[q] = fma2(wd, xgu[i * 10 + q], acc[q]);
        }
        ull* dst = reinterpret_cast<ull*>(ahg) + lane * 10;
        #pragma unroll
        for (int q = 0; q < 10; q++) dst[q] = lrelu2(acc[q]);
    }
    // ---- gate_map (lanes 0..19) ----
    if (lane < 20) {
        float acc = gate_b2[0];
        #pragma unroll
        for (int j = 0; j < 16; j++) {
            float v = g_bg1[j];
            #pragma unroll
            for (int i = 0; i < 6; i++) v += g_wg1[j * 6 + i] * xg[i * 20 + lane];
            v = v > 0.f ? v : NEG * v;
            acc += gate_w2[j] * v;
        }
        gm[g * 20 + lane] = 1.f / (1.f + __expf(-acc));
    }
    __syncwarp();

    // ---- phase 2: two k-halves with online softmax ----
    const int c0 = lane, c1 = lane + 32;
    const ull* gmr = reinterpret_cast<const ull*>(gm + g * 20);

    float M0 = -FLT_MAX, M1 = -FLT_MAX, MX0 = -FLT_MAX, MX1 = -FLT_MAX;
    ull SE0 = dup(0.f), SE1 = dup(0.f), SA0 = dup(0.f), SA1 = dup(0.f);

    half_pass<6, 0>(phg, ahg, xg, gmr, w2sh, wa2sh, pos_b2, attn_b2,
                    c0, c1, M0, M1, SE0, SE1, SA0, SA1, MX0, MX1);
    half_pass<4, 12>(phg, ahg, xg, gmr, w2sh, wa2sh, pos_b2, attn_b2,
                     c0, c1, M0, M1, SE0, SE1, SA0, SA1, MX0, MX1);

    {
        float a, bq, s, t;
        unpk(SA0, a, bq); unpk(SE0, s, t);
        outsh[c0 * 6 + g] = (a + bq) / (s + t) + MX0;
        unpk(SA1, a, bq); unpk(SE1, s, t);
        outsh[c1 * 6 + g] = (a + bq) / (s + t) + MX1;
    }
    __syncthreads();

    // coalesced-ish output: 64 ch x 4 n as float2 stores
    {
        int c = tid >> 1, h = (tid & 1) * 2;
        float2 v = make_float2(outsh[c * 6 + h], outsh[c * 6 + h + 1]);
        *reinterpret_cast<float2*>(out + ((size_t)b * 64 + c) * 8192 + n0 + h) = v;
    }
}

extern "C" void kernel_launch(void* const* d_in, const int* in_sizes, int n_in,
                              void* d_out, int out_size)
{
    (void)in_sizes; (void)n_in; (void)out_size;
    const float* x = (const float*)d_in[0];

    fold_kernel<<<1, 64>>>(
        (const float*)d_in[1], (const float*)d_in[2], (const float*)d_in[3],
        (const float*)d_in[4], (const float*)d_in[5],
        (const float*)d_in[6], (const float*)d_in[7], (const float*)d_in[8],
        (const float*)d_in[9], (const float*)d_in[10],
        (const float*)d_in[13], (const float*)d_in[14], (const float*)d_in[15],
        (const float*)d_in[16], (const float*)d_in[17],
        (const float*)d_in[20], (const float*)d_in[21], (const float*)d_in[22],
        (const float*)d_in[23], (const float*)d_in[24]);

    gsl_main_kernel<<<16384, 128>>>(
        x,
        (const float*)d_in[11], (const float*)d_in[12],   // pos_w2, pos_b2
        (const float*)d_in[18], (const float*)d_in[19],   // gate_w2, gate_b2
        (const float*)d_in[25], (const float*)d_in[26],   // attn_w2, attn_b2
        (float*)d_out);
}

// round 7
// speedup vs baseline: 2.5750x; 1.5732x over previous
#include <cuda_runtime.h>
#include <float.h>

#define EPS 1e-5f
#define NEG 0.2f

typedef unsigned long long ull;

__device__ __forceinline__ ull fma2(ull a, ull b, ull c) {
    ull d; asm("fma.rn.f32x2 %0, %1, %2, %3;" : "=l"(d) : "l"(a), "l"(b), "l"(c)); return d;
}
__device__ __forceinline__ ull add2(ull a, ull b) {
    ull d; asm("add.rn.f32x2 %0, %1, %2;" : "=l"(d) : "l"(a), "l"(b)); return d;
}
__device__ __forceinline__ ull mul2(ull a, ull b) {
    ull d; asm("mul.rn.f32x2 %0, %1, %2;" : "=l"(d) : "l"(a), "l"(b)); return d;
}
__device__ __forceinline__ ull pk(float lo, float hi) {
    ull r; asm("mov.b64 %0, {%1, %2};" : "=l"(r) : "f"(lo), "f"(hi)); return r;
}
__device__ __forceinline__ ull dup(float v) { return pk(v, v); }
__device__ __forceinline__ void unpk(ull v, float& lo, float& hi) {
    asm("mov.b64 {%0, %1}, %2;" : "=f"(lo), "=f"(hi) : "l"(v));
}
// lrelu(v) = 0.6*v + 0.4*|v|  (== v for v>0, 0.2v for v<0)
__device__ __forceinline__ ull lrelu2(ull v) {
    ull av = v & 0x7FFFFFFF7FFFFFFFULL;
    return fma2(dup(0.4f), av, mul2(dup(0.6f), v));
}

// BN-folded weights (setup kernel writes, main kernel reads)
__device__ float g_wt[64 * 6], g_bt[64];
__device__ float g_wp1[64 * 3], g_bp1[64];
__device__ float g_wg1[16 * 6], g_bg1[16];
__device__ float g_wa1[16 * 6], g_ba1[16];

__global__ void fold_kernel(
    const float* __restrict__ trans_w, const float* __restrict__ trans_g,
    const float* __restrict__ trans_b, const float* __restrict__ trans_m,
    const float* __restrict__ trans_v,
    const float* __restrict__ pos_w1, const float* __restrict__ pos_g,
    const float* __restrict__ pos_b, const float* __restrict__ pos_m,
    const float* __restrict__ pos_v,
    const float* __restrict__ gate_w1, const float* __restrict__ gate_g,
    const float* __restrict__ gate_b, const float* __restrict__ gate_m,
    const float* __restrict__ gate_v,
    const float* __restrict__ attn_w1, const float* __restrict__ attn_g,
    const float* __restrict__ attn_b, const float* __restrict__ attn_m,
    const float* __restrict__ attn_v)
{
    int i = threadIdx.x;
    if (i < 64) {
        float s = trans_g[i] * rsqrtf(trans_v[i] + EPS);
        #pragma unroll
        for (int j = 0; j < 6; j++) g_wt[i * 6 + j] = trans_w[i * 6 + j] * s;
        g_bt[i] = trans_b[i] - trans_m[i] * s;
        float sp = pos_g[i] * rsqrtf(pos_v[i] + EPS);
        #pragma unroll
        for (int j = 0; j < 3; j++) g_wp1[i * 3 + j] = pos_w1[i * 3 + j] * sp;
        g_bp1[i] = pos_b[i] - pos_m[i] * sp;
    }
    if (i < 16) {
        float sg = gate_g[i] * rsqrtf(gate_v[i] + EPS);
        #pragma unroll
        for (int j = 0; j < 6; j++) g_wg1[i * 6 + j] = gate_w1[i * 6 + j] * sg;
        g_bg1[i] = gate_b[i] - gate_m[i] * sg;
        float sa = attn_g[i] * rsqrtf(attn_v[i] + EPS);
        #pragma unroll
        for (int j = 0; j < 6; j++) g_wa1[i * 6 + j] = attn_w1[i * 6 + j] * sa;
        g_ba1[i] = attn_b[i] - attn_m[i] * sa;
    }
}

// Block = 128 threads = 4 n-positions (one warp each); each lane owns channels
// (lane, lane+32). k-dim (20) packed as 10 f32x2 pairs; shared rows read as
// float4. Phase-2 stages ordered (pe -> tfull -> al) so at most two 40-reg
// accumulator sets are ever live: fits 128 regs -> 4 CTAs/SM, no spills.
__global__ __launch_bounds__(128, 4) void gsl_main_kernel(
    const float* __restrict__ x,
    const float* __restrict__ pos_w2, const float* __restrict__ pos_b2,
    const float* __restrict__ gate_w2, const float* __restrict__ gate_b2,
    const float* __restrict__ attn_w2, const float* __restrict__ attn_b2,
    float* __restrict__ out)
{
    __shared__ __align__(16) float ph[4 * 64 * 20];   // [g][j][k]
    __shared__ __align__(16) float ah[4 * 16 * 20];   // [g][j][k]
    __shared__ __align__(16) float xsh[4 * 6 * 20];   // [g][ch][k]
    __shared__ __align__(16) float gm[4 * 20];        // [g][k]
    __shared__ float w2sh[64 * 65];                   // [j][c] padded
    __shared__ float wa2sh[16 * 65];                  // [j][c] padded
    __shared__ float outsh[64 * 6];                   // [c][g] padded stride 6

    const int tid = threadIdx.x;
    const int b = blockIdx.x >> 11;
    const int n0 = (blockIdx.x & 2047) << 2;

    // ---- cooperative loads: x tile + transposed weights ----
    const float* xb = x + ((size_t)b * 6 * 8192 + n0) * 20;
    for (int idx = tid; idx < 480; idx += 128) {
        int ch = idx / 80; int r = idx - ch * 80;          // r = g*20 + k
        xsh[(r / 20) * 120 + ch * 20 + (r % 20)] = xb[(size_t)ch * 8192 * 20 + r];
    }
    for (int idx = tid; idx < 4096; idx += 128) {
        int c = idx >> 6, j = idx & 63;
        w2sh[j * 65 + c] = pos_w2[idx];
    }
    for (int idx = tid; idx < 1024; idx += 128) {
        int c = idx >> 4, j = idx & 15;
        wa2sh[j * 65 + c] = attn_w2[idx];
    }
    __syncthreads();

    const int g = tid >> 5;
    const int lane = tid & 31;
    float* phg = ph + g * 1280;
    float* ahg = ah + g * 320;
    const float* xg = xsh + g * 120;

    // ---- phase 1 (warp-local): pos_h rows (lane, lane+32) ----
    {
        const ull* x3 = reinterpret_cast<const ull*>(xg + 60);
        #pragma unroll
        for (int rr = 0; rr < 2; rr++) {
            int j = lane + rr * 32;
            ull w0 = dup(g_wp1[j * 3 + 0]);
            ull w1 = dup(g_wp1[j * 3 + 1]);
            ull w2d = dup(g_wp1[j * 3 + 2]);
            ull bb = dup(g_bp1[j]);
            ull* dst = reinterpret_cast<ull*>(phg) + j * 10;
            #pragma unroll
            for (int q = 0; q < 10; q++) {
                ull v = fma2(w0, x3[q], bb);
                v = fma2(w1, x3[10 + q], v);
                v = fma2(w2d, x3[20 + q], v);
                dst[q] = lrelu2(v);
            }
        }
    }
    // ---- attn_h rows (lanes 0..15) ----
    if (lane < 16) {
        const ull* xrow = reinterpret_cast<const ull*>(xg);
        ull bb = dup(g_ba1[lane]);
        ull acc[10];
        #pragma unroll
        for (int q = 0; q < 10; q++) acc[q] = bb;
        #pragma unroll
        for (int i = 0; i < 6; i++) {
            ull wd = dup(g_wa1[lane * 6 + i]);
            #pragma unroll
            for (int q = 0; q < 10; q++) acc[q] = fma2(wd, xrow[i * 10 + q], acc[q]);
        }
        ull* dst = reinterpret_cast<ull*>(ahg) + lane * 10;
        #pragma unroll
        for (int q = 0; q < 10; q++) dst[q] = lrelu2(acc[q]);
    }
    // ---- gate_map (lanes 0..19) ----
    if (lane < 20) {
        float acc = gate_b2[0];
        #pragma unroll
        for (int j = 0; j < 16; j++) {
            float v = g_bg1[j];
            #pragma unroll
            for (int i = 0; i < 6; i++) v += g_wg1[j * 6 + i] * xg[i * 20 + lane];
            v = v > 0.f ? v : NEG * v;
            acc += gate_w2[j] * v;
        }
        gm[g * 20 + lane] = 1.f / (1.f + __expf(-acc));
    }
    __syncwarp();

    // ---- phase 2 ----
    const int c0 = lane, c1 = lane + 32;

    // (a) pos_enc accumulators
    ull pe0[10], pe1[10];
    {
        ull B0 = dup(pos_b2[c0]), B1 = dup(pos_b2[c1]);
        #pragma unroll
        for (int kp = 0; kp < 10; kp++) { pe0[kp] = B0; pe1[kp] = B1; }
    }
    #pragma unroll 2
    for (int jc = 0; jc < 8; ++jc) {
        ull w0[8], w1[8];
        #pragma unroll
        for (int t = 0; t < 8; t++) {
            int j = jc * 8 + t;
            w0[t] = dup(w2sh[j * 65 + c0]);
            w1[t] = dup(w2sh[j * 65 + c1]);
        }
        #pragma unroll
        for (int t = 0; t < 8; t++) {
            const float4* row = reinterpret_cast<const float4*>(phg + (jc * 8 + t) * 20);
            #pragma unroll
            for (int q = 0; q < 5; q++) {
                float4 p = row[q];
                ull plo = pk(p.x, p.y), phi = pk(p.z, p.w);
                pe0[2 * q]     = fma2(w0[t], plo, pe0[2 * q]);
                pe0[2 * q + 1] = fma2(w0[t], phi, pe0[2 * q + 1]);
                pe1[2 * q]     = fma2(w1[t], plo, pe1[2 * q]);
                pe1[2 * q + 1] = fma2(w1[t], phi, pe1[2 * q + 1]);
            }
        }
    }

    // (b) trans conv, folded immediately: tfull = lrelu(trans) + pos_enc
    ull tf0[10], tf1[10];
    {
        ull B0 = dup(g_bt[c0]), B1 = dup(g_bt[c1]);
        #pragma unroll
        for (int kp = 0; kp < 10; kp++) { tf0[kp] = B0; tf1[kp] = B1; }
        #pragma unroll
        for (int i = 0; i < 6; i++) {
            ull wt0 = dup(g_wt[c0 * 6 + i]), wt1 = dup(g_wt[c1 * 6 + i]);
            const float4* row = reinterpret_cast<const float4*>(xg + i * 20);
            #pragma unroll
            for (int q = 0; q < 5; q++) {
                float4 p = row[q];
                ull plo = pk(p.x, p.y), phi = pk(p.z, p.w);
                tf0[2 * q]     = fma2(wt0, plo, tf0[2 * q]);
                tf0[2 * q + 1] = fma2(wt0, phi, tf0[2 * q + 1]);
                tf1[2 * q]     = fma2(wt1, plo, tf1[2 * q]);
                tf1[2 * q + 1] = fma2(wt1, phi, tf1[2 * q + 1]);
            }
        }
        #pragma unroll
        for (int kp = 0; kp < 10; kp++) {
            tf0[kp] = add2(lrelu2(tf0[kp]), pe0[kp]);
            tf1[kp] = add2(lrelu2(tf1[kp]), pe1[kp]);
        }
    }

    // (c) attn logits init consumes pe (pe dead after this)
    ull al0[10], al1[10];
    {
        ull B0 = dup(attn_b2[c0]), B1 = dup(attn_b2[c1]);
        #pragma unroll
        for (int kp = 0; kp < 10; kp++) {
            al0[kp] = add2(pe0[kp], B0);
            al1[kp] = add2(pe1[kp], B1);
        }
    }
    #pragma unroll 2
    for (int jc = 0; jc < 2; ++jc) {
        ull w0[8], w1[8];
        #pragma unroll
        for (int t = 0; t < 8; t++) {
            int j = jc * 8 + t;
            w0[t] = dup(wa2sh[j * 65 + c0]);
            w1[t] = dup(wa2sh[j * 65 + c1]);
        }
        #pragma unroll
        for (int t = 0; t < 8; t++) {
            const float4* row = reinterpret_cast<const float4*>(ahg + (jc * 8 + t) * 20);
            #pragma unroll
            for (int q = 0; q < 5; q++) {
                float4 p = row[q];
                ull plo = pk(p.x, p.y), phi = pk(p.z, p.w);
                al0[2 * q]     = fma2(w0[t], plo, al0[2 * q]);
                al0[2 * q + 1] = fma2(w0[t], phi, al0[2 * q + 1]);
                al1[2 * q]     = fma2(w1[t], plo, al1[2 * q]);
                al1[2 * q + 1] = fma2(w1[t], phi, al1[2 * q + 1]);
            }
        }
    }

    // (d) softmax: scalar max-reduce, exp in place, packed sum
    ull se0, se1;
    {
        float m0 = -FLT_MAX, m1 = -FLT_MAX;
        #pragma unroll
        for (int kp = 0; kp < 10; kp++) {
            float a, bq;
            unpk(al0[kp], a, bq); m0 = fmaxf(m0, fmaxf(a, bq));
            unpk(al1[kp], a, bq); m1 = fmaxf(m1, fmaxf(a, bq));
        }
        se0 = dup(0.f); se1 = dup(0.f);
        #pragma unroll
        for (int kp = 0; kp < 10; kp++) {
            float a, bq;
            unpk(al0[kp], a, bq);
            al0[kp] = pk(__expf(a - m0), __expf(bq - m0));
            se0 = add2(se0, al0[kp]);
            unpk(al1[kp], a, bq);
            al1[kp] = pk(__expf(a - m1), __expf(bq - m1));
            se1 = add2(se1, al1[kp]);
        }
    }

    // (e) epilogue: sa += tfull*e; mx = max(tfull*gm)
    {
        ull sa0 = dup(0.f), sa1 = dup(0.f);
        float mx0 = -FLT_MAX, mx1 = -FLT_MAX;
        const ull* gmr = reinterpret_cast<const ull*>(gm + g * 20);
        #pragma unroll
        for (int kp = 0; kp < 10; kp++) {
            ull gk = gmr[kp];
            float a, bq;
            sa0 = fma2(tf0[kp], al0[kp], sa0);
            unpk(mul2(tf0[kp], gk), a, bq);
            mx0 = fmaxf(mx0, fmaxf(a, bq));
            sa1 = fma2(tf1[kp], al1[kp], sa1);
            unpk(mul2(tf1[kp], gk), a, bq);
            mx1 = fmaxf(mx1, fmaxf(a, bq));
        }
        float a, bq, s, t;
        unpk(sa0, a, bq); unpk(se0, s, t);
        outsh[c0 * 6 + g] = (a + bq) / (s + t) + mx0;
        unpk(sa1, a, bq); unpk(se1, s, t);
        outsh[c1 * 6 + g] = (a + bq) / (s + t) + mx1;
    }
    __syncthreads();

    // coalesced-ish output: 64 ch x 4 n as float2 stores
    {
        int c = tid >> 1, h = (tid & 1) * 2;
        float2 v = make_float2(outsh[c * 6 + h], outsh[c * 6 + h + 1]);
        *reinterpret_cast<float2*>(out + ((size_t)b * 64 + c) * 8192 + n0 + h) = v;
    }
}

extern "C" void kernel_launch(void* const* d_in, const int* in_sizes, int n_in,
                              void* d_out, int out_size)
{
    (void)in_sizes; (void)n_in; (void)out_size;
    const float* x = (const float*)d_in[0];

    fold_kernel<<<1, 64>>>(
        (const float*)d_in[1], (const float*)d_in[2], (const float*)d_in[3],
        (const float*)d_in[4], (const float*)d_in[5],
        (const float*)d_in[6], (const float*)d_in[7], (const float*)d_in[8],
        (const float*)d_in[9], (const float*)d_in[10],
        (const float*)d_in[13], (const float*)d_in[14], (const float*)d_in[15],
        (const float*)d_in[16], (const float*)d_in[17],
        (const float*)d_in[20], (const float*)d_in[21], (const float*)d_in[22],
        (const float*)d_in[23], (const float*)d_in[24]);

    gsl_main_kernel<<<16384, 128>>>(
        x,
        (const float*)d_in[11], (const float*)d_in[12],   // pos_w2, pos_b2
        (const float*)d_in[18], (const float*)d_in[19],   // gate_w2, gate_b2
        (const float*)d_in[25], (const float*)d_in[26],   // attn_w2, attn_b2
        (float*)d_out);
}